// round 9
// baseline (speedup 1.0000x reference)
#include <cuda_runtime.h>
#include <cuda_fp16.h>
#include <cstdint>

#define NUM_CODES 512
#define DIMS      64
#define HT        4096
#define N_VEC     131072
#define ZQ_SIZE   8388608
#define CTA_M     256
#define THREADS   256
#define GRID      148
#define NTILES    512

// ---- dynamic smem layout (bytes), MMA regions 1024-aligned for SW128 ----
#define SM_AHI   0
#define SM_ALO   32768
#define SM_BHI   65536
#define SM_BLO   131072
#define SM_BI    196608
#define SM_WSUM  197632
#define SM_RED   197696          // 512 floats for in-kernel finalize
#define SMEM_TOTAL 199744

__device__ float g_part[GRID];        // zero-init; overwritten every call
__device__ int   g_counts[NUM_CODES]; // zero-init; reset by finalize branch
__device__ int   g_done;              // zero-init; reset by finalize branch

#define SW(x) ((x) ^ ((((uint32_t)(x)) >> 3) & 0x70))

__device__ __forceinline__ uint32_t smem_u32(const void* p) {
    uint32_t a;
    asm("{ .reg .u64 t; cvta.to.shared.u64 t, %1; cvt.u32.u64 %0, t; }" : "=r"(a) : "l"(p));
    return a;
}
__device__ __forceinline__ void ldsm_x4(uint32_t& r0, uint32_t& r1, uint32_t& r2, uint32_t& r3, uint32_t a) {
    asm volatile("ldmatrix.sync.aligned.m8n8.x4.shared.b16 {%0,%1,%2,%3}, [%4];"
                 : "=r"(r0), "=r"(r1), "=r"(r2), "=r"(r3) : "r"(a));
}
__device__ __forceinline__ void mma16816(float* c, const uint32_t* a, uint32_t b0, uint32_t b1) {
    asm volatile("mma.sync.aligned.m16n8k16.row.col.f32.f16.f16.f32 "
                 "{%0,%1,%2,%3}, {%4,%5,%6,%7}, {%8,%9}, {%0,%1,%2,%3};"
                 : "+f"(c[0]), "+f"(c[1]), "+f"(c[2]), "+f"(c[3])
                 : "r"(a[0]), "r"(a[1]), "r"(a[2]), "r"(a[3]), "r"(b0), "r"(b1));
}
__device__ __forceinline__ uint32_t h2u(__half2 h) { return reinterpret_cast<uint32_t&>(h); }
__device__ __forceinline__ float2   u2f(uint32_t u) { __half2 h = reinterpret_cast<__half2&>(u); return __half22float2(h); }

__global__ __launch_bounds__(THREADS, 1) void vq_main(
    const float* __restrict__ z_e, const float* __restrict__ embed,
    float* __restrict__ out)
{
    extern __shared__ char smem[];
    const uint32_t sbase = smem_u32(smem);
    const int tid = threadIdx.x, wid = tid >> 5, lid = tid & 31;

    // ---------- B fill ONCE: embedding (512x64 fp32) -> f16 hi/lo, SW128 ----------
    {
        const float4* e4 = (const float4*)embed;
        #pragma unroll 8
        for (int i = tid; i < NUM_CODES * DIMS / 4; i += THREADS) {
            float4 f = e4[i];
            int row = i >> 4, dg = i & 15;
            __half hx = __float2half_rn(f.x), hy = __float2half_rn(f.y);
            __half hz = __float2half_rn(f.z), hw = __float2half_rn(f.w);
            __half lx = __float2half_rn(f.x - __half2float(hx));
            __half ly = __float2half_rn(f.y - __half2float(hy));
            __half lz = __float2half_rn(f.z - __half2float(hz));
            __half lw = __float2half_rn(f.w - __half2float(hw));
            uint32_t off = SW(row * 128 + dg * 8);
            *(uint2*)(smem + SM_BHI + off) = make_uint2(h2u(__halves2half2(hx, hy)), h2u(__halves2half2(hz, hw)));
            *(uint2*)(smem + SM_BLO + off) = make_uint2(h2u(__halves2half2(lx, ly)), h2u(__halves2half2(lz, lw)));
        }
    }

    const int rbase = wid * 32;
    const uint32_t brow = ((lid >> 4) << 3) + (lid & 7);
    const uint32_t bk_off = ((lid >> 3) & 1) << 4;
    int* sBI = (int*)(smem + SM_BI);
    float csum_total = 0.f;

    // B ldsm prefetch by flat index: idx = ntp*4 + kt, 0..127
#define LOADB(dh, dl, idx) do {                                                   \
        int _ntp = (idx) >> 2, _kt = (idx) & 3;                                   \
        uint32_t _sw = SW((uint32_t)((_ntp * 16 + brow) * 128 + _kt * 32 + bk_off)); \
        ldsm_x4((dh)[0], (dh)[1], (dh)[2], (dh)[3], sbase + SM_BHI + _sw);        \
        ldsm_x4((dl)[0], (dl)[1], (dl)[2], (dl)[3], sbase + SM_BLO + _sw);        \
    } while (0)

    // ================= persistent tile loop =================
    for (int tile = blockIdx.x; tile < NTILES; tile += GRID) {
        // ---------- A fill: this thread's z vector -> f16 hi/lo, SW128 ----------
        const int n = tile * CTA_M + tid;
        const int b = n >> 12, r = n & 4095;
        const float* zp = z_e + (size_t)b * (DIMS * HT) + r;

        #pragma unroll
        for (int i = 0; i < 8; i++) {
            uint32_t zh[4], zl[4];
            #pragma unroll
            for (int j = 0; j < 4; j++) {
                float x0 = zp[(8 * i + 2 * j) * HT];
                float x1 = zp[(8 * i + 2 * j + 1) * HT];
                __half h0 = __float2half_rn(x0), h1 = __float2half_rn(x1);
                __half l0 = __float2half_rn(x0 - __half2float(h0));
                __half l1 = __float2half_rn(x1 - __half2float(h1));
                zh[j] = h2u(__halves2half2(h0, h1));
                zl[j] = h2u(__halves2half2(l0, l1));
            }
            uint32_t off = SW(tid * 128 + i * 16);
            *(uint4*)(smem + SM_AHI + off) = make_uint4(zh[0], zh[1], zh[2], zh[3]);
            *(uint4*)(smem + SM_ALO + off) = make_uint4(zl[0], zl[1], zl[2], zl[3]);
        }
        __syncthreads();   // A (and on iter 0, B) ready

        // ---------- A fragments (2 m-tiles per warp) ----------
        uint32_t a_hi[2][4][4], a_lo[2][4][4];
        {
            const int g = lid >> 3;
            #pragma unroll
            for (int mt = 0; mt < 2; mt++)
                #pragma unroll
                for (int kt = 0; kt < 4; kt++) {
                    uint32_t row = rbase + mt * 16 + ((g & 1) << 3) + (lid & 7);
                    uint32_t sw = SW(row * 128 + kt * 32 + ((g >> 1) << 4));
                    ldsm_x4(a_hi[mt][kt][0], a_hi[mt][kt][1], a_hi[mt][kt][2], a_hi[mt][kt][3],
                            sbase + SM_AHI + sw);
                    ldsm_x4(a_lo[mt][kt][0], a_lo[mt][kt][1], a_lo[mt][kt][2], a_lo[mt][kt][3],
                            sbase + SM_ALO + sw);
                }
        }

        // ---------- main loop: 32 n-tile pairs, 3-pass, split accumulators, B prefetch ----------
        float m1[4] = {-3.4e38f, -3.4e38f, -3.4e38f, -3.4e38f};
        int   i1[4] = {0, 0, 0, 0};

        uint32_t bhA[4], blA[4], bhB[4], blB[4];   // double buffer (even idx -> A, odd -> B)
        LOADB(bhA, blA, 0);

        #pragma unroll 1
        for (int ntp = 0; ntp < 32; ntp++) {
            // aP[pass][h][mt][i] : 12 independent depth-4 chains
            float aP[3][2][2][4];
            #pragma unroll
            for (int p = 0; p < 3; p++)
                #pragma unroll
                for (int h = 0; h < 2; h++)
                    #pragma unroll
                    for (int mt = 0; mt < 2; mt++)
                        #pragma unroll
                        for (int i = 0; i < 4; i++) aP[p][h][mt][i] = 0.f;

            #pragma unroll
            for (int kt = 0; kt < 4; kt++) {
                const int idx = ntp * 4 + kt;
                const int nidx = (idx + 1 < 128) ? idx + 1 : 127;
                uint32_t *ch, *cl, *nh, *nl;
                if (kt & 1) { ch = bhB; cl = blB; nh = bhA; nl = blA; }
                else        { ch = bhA; cl = blA; nh = bhB; nl = blB; }
                LOADB(nh, nl, nidx);   // prefetch next kt (or next ntp's kt0)
                #pragma unroll
                for (int mt = 0; mt < 2; mt++) {
                    mma16816(aP[0][0][mt], a_hi[mt][kt], ch[0], ch[1]);
                    mma16816(aP[0][1][mt], a_hi[mt][kt], ch[2], ch[3]);
                    mma16816(aP[1][0][mt], a_hi[mt][kt], cl[0], cl[1]);
                    mma16816(aP[1][1][mt], a_hi[mt][kt], cl[2], cl[3]);
                    mma16816(aP[2][0][mt], a_lo[mt][kt], ch[0], ch[1]);
                    mma16816(aP[2][1][mt], a_lo[mt][kt], ch[2], ch[3]);
                }
            }

            #pragma unroll
            for (int h = 0; h < 2; h++)
                #pragma unroll
                for (int mt = 0; mt < 2; mt++)
                    #pragma unroll
                    for (int i = 0; i < 4; i++) {
                        int s = mt * 2 + (i >> 1);
                        int k = ntp * 16 + h * 8 + 2 * (lid & 3) + (i & 1);
                        float dot = aP[0][h][mt][i] + aP[1][h][mt][i] + aP[2][h][mt][i];
                        if (dot > m1[s]) { m1[s] = dot; i1[s] = k; }
                    }
        }

        // ---------- merge max(dot) across the 4 quad lanes ----------
        #pragma unroll
        for (int off = 1; off <= 2; off <<= 1) {
            #pragma unroll
            for (int s = 0; s < 4; s++) {
                float om = __shfl_xor_sync(0xffffffffu, m1[s], off);
                int   oi = __shfl_xor_sync(0xffffffffu, i1[s], off);
                bool take = (om > m1[s]) || (om == m1[s] && oi < i1[s]);
                if (take) { m1[s] = om; i1[s] = oi; }
            }
        }
        if ((lid & 3) == 0) {
            #pragma unroll
            for (int s = 0; s < 4; s++) {
                int row = rbase + (s >> 1) * 16 + (s & 1) * 8 + (lid >> 2);
                sBI[row] = i1[s];
            }
        }
        __syncthreads();

        // ---------- outputs (row = tid) ----------
        const int bi = sBI[tid];
        float* op = out + (size_t)b * (DIMS * HT) + r;
        float csum = 0.f;
        #pragma unroll
        for (int dg = 0; dg < 16; dg++) {
            uint32_t zo = SW(tid * 128 + dg * 8);
            uint2 zh = *(uint2*)(smem + SM_AHI + zo);
            uint2 zl = *(uint2*)(smem + SM_ALO + zo);
            float2 z01 = u2f(zh.x), zl01 = u2f(zl.x), z23 = u2f(zh.y), zl23 = u2f(zl.y);
            float zv0 = z01.x + zl01.x, zv1 = z01.y + zl01.y;
            float zv2 = z23.x + zl23.x, zv3 = z23.y + zl23.y;
            uint32_t qo = SW(bi * 128 + dg * 8);
            uint2 qh = *(uint2*)(smem + SM_BHI + qo);
            uint2 ql = *(uint2*)(smem + SM_BLO + qo);
            float2 e01 = u2f(qh.x), el01 = u2f(ql.x), e23 = u2f(qh.y), el23 = u2f(ql.y);
            float q0 = e01.x + el01.x, q1 = e01.y + el01.y, q2 = e23.x + el23.x, q3 = e23.y + el23.y;
            float d0 = q0 - zv0, d1v = q1 - zv1, d2v = q2 - zv2, d3 = q3 - zv3;
            op[(4 * dg + 0) * HT] = zv0 + d0;
            op[(4 * dg + 1) * HT] = zv1 + d1v;
            op[(4 * dg + 2) * HT] = zv2 + d2v;
            op[(4 * dg + 3) * HT] = zv3 + d3;
            csum += d0 * d0 + d1v * d1v + d2v * d2v + d3 * d3;
        }
        out[ZQ_SIZE + 1 + n] = (float)bi;
        atomicAdd(&g_counts[bi], 1);
        csum_total += csum;

        __syncthreads();   // protect A smem / sBI before next tile
    }

    // ---------- per-CTA commitment partial ----------
    #pragma unroll
    for (int off = 16; off; off >>= 1)
        csum_total += __shfl_down_sync(0xffffffffu, csum_total, off);
    float* wsum = (float*)(smem + SM_WSUM);
    if (lid == 0) wsum[wid] = csum_total;
    __syncthreads();
    if (tid == 0) {
        float s = 0.f;
        #pragma unroll
        for (int w = 0; w < 8; w++) s += wsum[w];
        g_part[blockIdx.x] = s;
    }

    // ---------- last-CTA in-kernel finalize ----------
    __threadfence();
    __shared__ int s_last;
    if (tid == 0) s_last = (atomicAdd(&g_done, 1) == GRID - 1);
    __syncthreads();
    if (s_last) {
        __threadfence();
        float* red = (float*)(smem + SM_RED);

        // commitment
        red[tid] = (tid < GRID) ? g_part[tid] : 0.f;
        __syncthreads();
        #pragma unroll
        for (int off = 128; off; off >>= 1) {
            if (tid < off) red[tid] += red[tid + off];
            __syncthreads();
        }
        if (tid == 0) out[ZQ_SIZE] = 0.25f * red[0] / (float)ZQ_SIZE;
        __syncthreads();

        // entropy -> perplexity (512 codes, 2 per thread)
        const int c0 = g_counts[tid], c1 = g_counts[tid + 256];
        {
            float p0 = (float)c0 / (float)N_VEC, p1 = (float)c1 / (float)N_VEC;
            red[tid] = -p0 * logf(p0 + 1e-12f) - p1 * logf(p1 + 1e-12f);
        }
        __syncthreads();
        #pragma unroll
        for (int off = 128; off; off >>= 1) {
            if (tid < off) red[tid] += red[tid + off];
            __syncthreads();
        }
        if (tid == 0) out[ZQ_SIZE + 1 + N_VEC] = expf(red[0]);
        __syncthreads();

        // usage
        red[tid] = ((c0 > 0) ? 1.f : 0.f) + ((c1 > 0) ? 1.f : 0.f);
        __syncthreads();
        #pragma unroll
        for (int off = 128; off; off >>= 1) {
            if (tid < off) red[tid] += red[tid + off];
            __syncthreads();
        }
        if (tid == 0) out[ZQ_SIZE + 1 + N_VEC + 1] = red[0] / (float)NUM_CODES;

        // reset state for next graph replay
        g_counts[tid] = 0;
        g_counts[tid + 256] = 0;
        if (tid == 0) g_done = 0;
    }
}

extern "C" void kernel_launch(void* const* d_in, const int* in_sizes, int n_in,
                              void* d_out, int out_size) {
    const float* z_e   = (const float*)d_in[0];
    const float* embed = (const float*)d_in[1];
    float* out = (float*)d_out;

    cudaFuncSetAttribute(vq_main, cudaFuncAttributeMaxDynamicSharedMemorySize, SMEM_TOTAL);
    vq_main<<<GRID, THREADS, SMEM_TOTAL>>>(z_e, embed, out);
}

// round 10
// speedup vs baseline: 1.0535x; 1.0535x over previous
#include <cuda_runtime.h>
#include <cuda_fp16.h>
#include <cstdint>

#define NUM_CODES 512
#define DIMS      64
#define HT        4096
#define N_VEC     131072
#define ZQ_SIZE   8388608
#define CTA_M     256
#define THREADS   256
#define GRID      148
#define NTILES    512

// ---- dynamic smem layout (bytes), MMA regions 1024-aligned for SW128 ----
#define SM_AHI   0
#define SM_ALO   32768
#define SM_BHI   65536
#define SM_BLO   131072
#define SM_BI    196608
#define SM_WSUM  197632
#define SM_RED   197696          // 512 floats for in-kernel finalize
#define SMEM_TOTAL 199744

__device__ float g_part[GRID];        // zero-init; overwritten every call
__device__ int   g_counts[NUM_CODES]; // zero-init; reset by finalize branch
__device__ int   g_done;              // zero-init; reset by finalize branch

#define SW(x) ((x) ^ ((((uint32_t)(x)) >> 3) & 0x70))

__device__ __forceinline__ uint32_t smem_u32(const void* p) {
    uint32_t a;
    asm("{ .reg .u64 t; cvta.to.shared.u64 t, %1; cvt.u32.u64 %0, t; }" : "=r"(a) : "l"(p));
    return a;
}
__device__ __forceinline__ void ldsm_x4(uint32_t& r0, uint32_t& r1, uint32_t& r2, uint32_t& r3, uint32_t a) {
    asm volatile("ldmatrix.sync.aligned.m8n8.x4.shared.b16 {%0,%1,%2,%3}, [%4];"
                 : "=r"(r0), "=r"(r1), "=r"(r2), "=r"(r3) : "r"(a));
}
__device__ __forceinline__ void mma16816(float* c, const uint32_t* a, uint32_t b0, uint32_t b1) {
    asm volatile("mma.sync.aligned.m16n8k16.row.col.f32.f16.f16.f32 "
                 "{%0,%1,%2,%3}, {%4,%5,%6,%7}, {%8,%9}, {%0,%1,%2,%3};"
                 : "+f"(c[0]), "+f"(c[1]), "+f"(c[2]), "+f"(c[3])
                 : "r"(a[0]), "r"(a[1]), "r"(a[2]), "r"(a[3]), "r"(b0), "r"(b1));
}
__device__ __forceinline__ uint32_t h2u(__half2 h) { return reinterpret_cast<uint32_t&>(h); }
__device__ __forceinline__ float2   u2f(uint32_t u) { __half2 h = reinterpret_cast<__half2&>(u); return __half22float2(h); }

__global__ __launch_bounds__(THREADS, 1) void vq_main(
    const float* __restrict__ z_e, const float* __restrict__ embed,
    float* __restrict__ out)
{
    extern __shared__ char smem[];
    const uint32_t sbase = smem_u32(smem);
    const int tid = threadIdx.x, wid = tid >> 5, lid = tid & 31;

    // ---------- B fill ONCE: embedding (512x64 fp32) -> f16 hi/lo, SW128 ----------
    {
        const float4* e4 = (const float4*)embed;
        #pragma unroll 8
        for (int i = tid; i < NUM_CODES * DIMS / 4; i += THREADS) {
            float4 f = e4[i];
            int row = i >> 4, dg = i & 15;
            __half hx = __float2half_rn(f.x), hy = __float2half_rn(f.y);
            __half hz = __float2half_rn(f.z), hw = __float2half_rn(f.w);
            __half lx = __float2half_rn(f.x - __half2float(hx));
            __half ly = __float2half_rn(f.y - __half2float(hy));
            __half lz = __float2half_rn(f.z - __half2float(hz));
            __half lw = __float2half_rn(f.w - __half2float(hw));
            uint32_t off = SW(row * 128 + dg * 8);
            *(uint2*)(smem + SM_BHI + off) = make_uint2(h2u(__halves2half2(hx, hy)), h2u(__halves2half2(hz, hw)));
            *(uint2*)(smem + SM_BLO + off) = make_uint2(h2u(__halves2half2(lx, ly)), h2u(__halves2half2(lz, lw)));
        }
    }

    const int rbase = wid * 32;
    const uint32_t brow = ((lid >> 4) << 3) + (lid & 7);
    const uint32_t bk_off = ((lid >> 3) & 1) << 4;
    int* sBI = (int*)(smem + SM_BI);
    float csum_total = 0.f;

    // ---------- prefetch first tile's z into registers ----------
    float zraw[32];
    {
        const int n0 = blockIdx.x * CTA_M + tid;
        const int b0 = n0 >> 12, r0 = n0 & 4095;
        const float* zp0 = z_e + (size_t)b0 * (DIMS * HT) + r0;
        #pragma unroll
        for (int d = 0; d < 32; d++) zraw[d] = zp0[(size_t)(2 * d) * HT],
                                     zraw[d] = zraw[d];  // keep simple; pairs loaded below
        // load both halves: re-issue full 64? hold even dims here, odd loaded in convert?
    }
    // NOTE: we hold dims as 32 float2-pairs worth via two arrays to cover all 64 dims
    float zraw2[32];
    {
        const int n0 = blockIdx.x * CTA_M + tid;
        const int b0 = n0 >> 12, r0 = n0 & 4095;
        const float* zp0 = z_e + (size_t)b0 * (DIMS * HT) + r0;
        #pragma unroll
        for (int d = 0; d < 32; d++) zraw2[d] = zp0[(size_t)(2 * d + 1) * HT];
    }

    // ================= persistent tile loop =================
    for (int tile = blockIdx.x; tile < NTILES; tile += GRID) {
        const int n = tile * CTA_M + tid;
        const int b = n >> 12, r = n & 4095;

        // ---------- A fill from registers -> f16 hi/lo, SW128 ----------
        #pragma unroll
        for (int i = 0; i < 8; i++) {
            uint32_t zh[4], zl[4];
            #pragma unroll
            for (int j = 0; j < 4; j++) {
                float x0 = zraw[4 * i + j];
                float x1 = zraw2[4 * i + j];
                __half h0 = __float2half_rn(x0), h1 = __float2half_rn(x1);
                __half l0 = __float2half_rn(x0 - __half2float(h0));
                __half l1 = __float2half_rn(x1 - __half2float(h1));
                zh[j] = h2u(__halves2half2(h0, h1));
                zl[j] = h2u(__halves2half2(l0, l1));
            }
            uint32_t off = SW(tid * 128 + i * 16);
            *(uint4*)(smem + SM_AHI + off) = make_uint4(zh[0], zh[1], zh[2], zh[3]);
            *(uint4*)(smem + SM_ALO + off) = make_uint4(zl[0], zl[1], zl[2], zl[3]);
        }
        __syncthreads();   // A (and on iter 0, B) ready

        // ---------- A fragments (2 m-tiles per warp) ----------
        uint32_t a_hi[2][4][4], a_lo[2][4][4];
        {
            const int g = lid >> 3;
            #pragma unroll
            for (int mt = 0; mt < 2; mt++)
                #pragma unroll
                for (int kt = 0; kt < 4; kt++) {
                    uint32_t row = rbase + mt * 16 + ((g & 1) << 3) + (lid & 7);
                    uint32_t sw = SW(row * 128 + kt * 32 + ((g >> 1) << 4));
                    ldsm_x4(a_hi[mt][kt][0], a_hi[mt][kt][1], a_hi[mt][kt][2], a_hi[mt][kt][3],
                            sbase + SM_AHI + sw);
                    ldsm_x4(a_lo[mt][kt][0], a_lo[mt][kt][1], a_lo[mt][kt][2], a_lo[mt][kt][3],
                            sbase + SM_ALO + sw);
                }
        }

        // ---------- issue next tile's z LDGs (overlap with mainloop) ----------
        {
            int ntile = tile + GRID;
            if (ntile >= NTILES) ntile = tile;       // dummy valid address
            const int nn = ntile * CTA_M + tid;
            const int nb = nn >> 12, nr = nn & 4095;
            const float* znp = z_e + (size_t)nb * (DIMS * HT) + nr;
            #pragma unroll
            for (int d = 0; d < 32; d++) {
                zraw[d]  = __ldg(znp + (size_t)(2 * d) * HT);
                zraw2[d] = __ldg(znp + (size_t)(2 * d + 1) * HT);
            }
        }

        // ---------- main loop: 32 n-tile pairs, 3-pass, argmax(dot) ----------
        float m1[4] = {-3.4e38f, -3.4e38f, -3.4e38f, -3.4e38f};
        int   i1[4] = {0, 0, 0, 0};

        #pragma unroll 2
        for (int ntp = 0; ntp < 32; ntp++) {
            float acc[2][2][4] = {{{0.f,0.f,0.f,0.f},{0.f,0.f,0.f,0.f}},
                                  {{0.f,0.f,0.f,0.f},{0.f,0.f,0.f,0.f}}};
            #pragma unroll
            for (int kt = 0; kt < 4; kt++) {
                uint32_t byte = (ntp * 16 + brow) * 128 + kt * 32 + bk_off;
                uint32_t sw = SW(byte);
                uint32_t bh0, bh1, bh2, bh3, bl0, bl1, bl2, bl3;
                ldsm_x4(bh0, bh1, bh2, bh3, sbase + SM_BHI + sw);
                ldsm_x4(bl0, bl1, bl2, bl3, sbase + SM_BLO + sw);
                #pragma unroll
                for (int mt = 0; mt < 2; mt++) {
                    mma16816(acc[0][mt], a_hi[mt][kt], bh0, bh1);
                    mma16816(acc[1][mt], a_hi[mt][kt], bh2, bh3);
                    mma16816(acc[0][mt], a_hi[mt][kt], bl0, bl1);
                    mma16816(acc[1][mt], a_hi[mt][kt], bl2, bl3);
                    mma16816(acc[0][mt], a_lo[mt][kt], bh0, bh1);
                    mma16816(acc[1][mt], a_lo[mt][kt], bh2, bh3);
                }
            }
            #pragma unroll
            for (int h = 0; h < 2; h++)
                #pragma unroll
                for (int mt = 0; mt < 2; mt++)
                    #pragma unroll
                    for (int i = 0; i < 4; i++) {
                        int s = mt * 2 + (i >> 1);
                        int k = ntp * 16 + h * 8 + 2 * (lid & 3) + (i & 1);
                        float dot = acc[h][mt][i];
                        if (dot > m1[s]) { m1[s] = dot; i1[s] = k; }
                    }
        }

        // ---------- merge max(dot) across the 4 quad lanes ----------
        #pragma unroll
        for (int off = 1; off <= 2; off <<= 1) {
            #pragma unroll
            for (int s = 0; s < 4; s++) {
                float om = __shfl_xor_sync(0xffffffffu, m1[s], off);
                int   oi = __shfl_xor_sync(0xffffffffu, i1[s], off);
                bool take = (om > m1[s]) || (om == m1[s] && oi < i1[s]);
                if (take) { m1[s] = om; i1[s] = oi; }
            }
        }
        if ((lid & 3) == 0) {
            #pragma unroll
            for (int s = 0; s < 4; s++) {
                int row = rbase + (s >> 1) * 16 + (s & 1) * 8 + (lid >> 2);
                sBI[row] = i1[s];
            }
        }
        __syncthreads();

        // ---------- outputs (row = tid) ----------
        const int bi = sBI[tid];
        float* op = out + (size_t)b * (DIMS * HT) + r;
        float csum = 0.f;
        #pragma unroll
        for (int dg = 0; dg < 16; dg++) {
            uint32_t zo = SW(tid * 128 + dg * 8);
            uint2 zh = *(uint2*)(smem + SM_AHI + zo);
            uint2 zl = *(uint2*)(smem + SM_ALO + zo);
            float2 z01 = u2f(zh.x), zl01 = u2f(zl.x), z23 = u2f(zh.y), zl23 = u2f(zl.y);
            float zv0 = z01.x + zl01.x, zv1 = z01.y + zl01.y;
            float zv2 = z23.x + zl23.x, zv3 = z23.y + zl23.y;
            uint32_t qo = SW(bi * 128 + dg * 8);
            uint2 qh = *(uint2*)(smem + SM_BHI + qo);
            uint2 ql = *(uint2*)(smem + SM_BLO + qo);
            float2 e01 = u2f(qh.x), el01 = u2f(ql.x), e23 = u2f(qh.y), el23 = u2f(ql.y);
            float q0 = e01.x + el01.x, q1 = e01.y + el01.y, q2 = e23.x + el23.x, q3 = e23.y + el23.y;
            float d0 = q0 - zv0, d1v = q1 - zv1, d2v = q2 - zv2, d3 = q3 - zv3;
            op[(4 * dg + 0) * HT] = zv0 + d0;
            op[(4 * dg + 1) * HT] = zv1 + d1v;
            op[(4 * dg + 2) * HT] = zv2 + d2v;
            op[(4 * dg + 3) * HT] = zv3 + d3;
            csum += d0 * d0 + d1v * d1v + d2v * d2v + d3 * d3;
        }
        out[ZQ_SIZE + 1 + n] = (float)bi;
        atomicAdd(&g_counts[bi], 1);
        csum_total += csum;

        __syncthreads();   // protect A smem / sBI before next tile
    }

    // ---------- per-CTA commitment partial ----------
    #pragma unroll
    for (int off = 16; off; off >>= 1)
        csum_total += __shfl_down_sync(0xffffffffu, csum_total, off);
    float* wsum = (float*)(smem + SM_WSUM);
    if (lid == 0) wsum[wid] = csum_total;
    __syncthreads();
    if (tid == 0) {
        float s = 0.f;
        #pragma unroll
        for (int w = 0; w < 8; w++) s += wsum[w];
        g_part[blockIdx.x] = s;
    }

    // ---------- last-CTA in-kernel finalize ----------
    __threadfence();
    __shared__ int s_last;
    if (tid == 0) s_last = (atomicAdd(&g_done, 1) == GRID - 1);
    __syncthreads();
    if (s_last) {
        __threadfence();
        float* red = (float*)(smem + SM_RED);

        // commitment
        red[tid] = (tid < GRID) ? g_part[tid] : 0.f;
        __syncthreads();
        #pragma unroll
        for (int off = 128; off; off >>= 1) {
            if (tid < off) red[tid] += red[tid + off];
            __syncthreads();
        }
        if (tid == 0) out[ZQ_SIZE] = 0.25f * red[0] / (float)ZQ_SIZE;
        __syncthreads();

        // entropy -> perplexity (512 codes, 2 per thread)
        const int c0 = g_counts[tid], c1 = g_counts[tid + 256];
        {
            float p0 = (float)c0 / (float)N_VEC, p1 = (float)c1 / (float)N_VEC;
            red[tid] = -p0 * logf(p0 + 1e-12f) - p1 * logf(p1 + 1e-12f);
        }
        __syncthreads();
        #pragma unroll
        for (int off = 128; off; off >>= 1) {
            if (tid < off) red[tid] += red[tid + off];
            __syncthreads();
        }
        if (tid == 0) out[ZQ_SIZE + 1 + N_VEC] = expf(red[0]);
        __syncthreads();

        // usage
        red[tid] = ((c0 > 0) ? 1.f : 0.f) + ((c1 > 0) ? 1.f : 0.f);
        __syncthreads();
        #pragma unroll
        for (int off = 128; off; off >>= 1) {
            if (tid < off) red[tid] += red[tid + off];
            __syncthreads();
        }
        if (tid == 0) out[ZQ_SIZE + 1 + N_VEC + 1] = red[0] / (float)NUM_CODES;

        // reset state for next graph replay
        g_counts[tid] = 0;
        g_counts[tid + 256] = 0;
        if (tid == 0) g_done = 0;
    }
}

extern "C" void kernel_launch(void* const* d_in, const int* in_sizes, int n_in,
                              void* d_out, int out_size) {
    const float* z_e   = (const float*)d_in[0];
    const float* embed = (const float*)d_in[1];
    float* out = (float*)d_out;

    cudaFuncSetAttribute(vq_main, cudaFuncAttributeMaxDynamicSharedMemorySize, SMEM_TOTAL);
    vq_main<<<GRID, THREADS, SMEM_TOTAL>>>(z_e, embed, out);
}

// round 11
// speedup vs baseline: 1.0565x; 1.0028x over previous
#include <cuda_runtime.h>
#include <cuda_fp16.h>
#include <cstdint>

#define NUM_CODES 512
#define DIMS      64
#define HT        4096
#define N_VEC     131072
#define ZQ_SIZE   8388608
#define CTA_M     256
#define THREADS   256
#define GRID      148
#define NTILES    512

// ---- dynamic smem layout (bytes), MMA regions 1024-aligned for SW128 ----
#define SM_AHI   0
#define SM_ALO   32768
#define SM_BHI   65536
#define SM_BLO   131072
#define SM_WSUM  196608
#define SM_RED   196672          // 512 floats for in-kernel finalize
#define SMEM_TOTAL 198720

__device__ float g_part[GRID];        // zero-init; overwritten every call
__device__ int   g_counts[NUM_CODES]; // zero-init; reset by finalize branch
__device__ int   g_done;              // zero-init; reset by finalize branch

#define SW(x) ((x) ^ ((((uint32_t)(x)) >> 3) & 0x70))

__device__ __forceinline__ uint32_t smem_u32(const void* p) {
    uint32_t a;
    asm("{ .reg .u64 t; cvta.to.shared.u64 t, %1; cvt.u32.u64 %0, t; }" : "=r"(a) : "l"(p));
    return a;
}
__device__ __forceinline__ void ldsm_x4(uint32_t& r0, uint32_t& r1, uint32_t& r2, uint32_t& r3, uint32_t a) {
    asm volatile("ldmatrix.sync.aligned.m8n8.x4.shared.b16 {%0,%1,%2,%3}, [%4];"
                 : "=r"(r0), "=r"(r1), "=r"(r2), "=r"(r3) : "r"(a));
}
__device__ __forceinline__ void mma16816(float* c, const uint32_t* a, uint32_t b0, uint32_t b1) {
    asm volatile("mma.sync.aligned.m16n8k16.row.col.f32.f16.f16.f32 "
                 "{%0,%1,%2,%3}, {%4,%5,%6,%7}, {%8,%9}, {%0,%1,%2,%3};"
                 : "+f"(c[0]), "+f"(c[1]), "+f"(c[2]), "+f"(c[3])
                 : "r"(a[0]), "r"(a[1]), "r"(a[2]), "r"(a[3]), "r"(b0), "r"(b1));
}
__device__ __forceinline__ uint32_t h2u(__half2 h) { return reinterpret_cast<uint32_t&>(h); }
__device__ __forceinline__ float2   u2f(uint32_t u) { __half2 h = reinterpret_cast<__half2&>(u); return __half22float2(h); }

__global__ __launch_bounds__(THREADS, 1) void vq_main(
    const float* __restrict__ z_e, const float* __restrict__ embed,
    float* __restrict__ out)
{
    extern __shared__ char smem[];
    const uint32_t sbase = smem_u32(smem);
    const int tid = threadIdx.x, wid = tid >> 5, lid = tid & 31;

    // ---------- B fill ONCE: embedding (512x64 fp32) -> f16 hi/lo, SW128 ----------
    {
        const float4* e4 = (const float4*)embed;
        #pragma unroll 8
        for (int i = tid; i < NUM_CODES * DIMS / 4; i += THREADS) {
            float4 f = e4[i];
            int row = i >> 4, dg = i & 15;
            __half hx = __float2half_rn(f.x), hy = __float2half_rn(f.y);
            __half hz = __float2half_rn(f.z), hw = __float2half_rn(f.w);
            __half lx = __float2half_rn(f.x - __half2float(hx));
            __half ly = __float2half_rn(f.y - __half2float(hy));
            __half lz = __float2half_rn(f.z - __half2float(hz));
            __half lw = __float2half_rn(f.w - __half2float(hw));
            uint32_t off = SW(row * 128 + dg * 8);
            *(uint2*)(smem + SM_BHI + off) = make_uint2(h2u(__halves2half2(hx, hy)), h2u(__halves2half2(hz, hw)));
            *(uint2*)(smem + SM_BLO + off) = make_uint2(h2u(__halves2half2(lx, ly)), h2u(__halves2half2(lz, lw)));
        }
    }

    const int rbase = wid * 32;
    const uint32_t brow = ((lid >> 4) << 3) + (lid & 7);
    const uint32_t bk_off = ((lid >> 3) & 1) << 4;
    float csum_total = 0.f;

    // ---------- prefetch first tile's z into registers ----------
    float zraw[32], zraw2[32];
    {
        const int n0 = blockIdx.x * CTA_M + tid;
        const int b0 = n0 >> 12, r0 = n0 & 4095;
        const float* zp0 = z_e + (size_t)b0 * (DIMS * HT) + r0;
        #pragma unroll
        for (int d = 0; d < 32; d++) {
            zraw[d]  = zp0[(size_t)(2 * d) * HT];
            zraw2[d] = zp0[(size_t)(2 * d + 1) * HT];
        }
    }

    // ================= persistent tile loop =================
    for (int tile = blockIdx.x; tile < NTILES; tile += GRID) {
        const int n = tile * CTA_M + tid;
        const int b = n >> 12, r = n & 4095;

        // ---------- A fill from registers -> f16 hi/lo, SW128 ----------
        #pragma unroll
        for (int i = 0; i < 8; i++) {
            uint32_t zh[4], zl[4];
            #pragma unroll
            for (int j = 0; j < 4; j++) {
                float x0 = zraw[4 * i + j];
                float x1 = zraw2[4 * i + j];
                __half h0 = __float2half_rn(x0), h1 = __float2half_rn(x1);
                __half l0 = __float2half_rn(x0 - __half2float(h0));
                __half l1 = __float2half_rn(x1 - __half2float(h1));
                zh[j] = h2u(__halves2half2(h0, h1));
                zl[j] = h2u(__halves2half2(l0, l1));
            }
            uint32_t off = SW(tid * 128 + i * 16);
            *(uint4*)(smem + SM_AHI + off) = make_uint4(zh[0], zh[1], zh[2], zh[3]);
            *(uint4*)(smem + SM_ALO + off) = make_uint4(zl[0], zl[1], zl[2], zl[3]);
        }
        __syncthreads();   // A (and on iter 0, B) ready

        // ---------- A fragments (2 m-tiles per warp) ----------
        uint32_t a_hi[2][4][4], a_lo[2][4][4];
        {
            const int g = lid >> 3;
            #pragma unroll
            for (int mt = 0; mt < 2; mt++)
                #pragma unroll
                for (int kt = 0; kt < 4; kt++) {
                    uint32_t row = rbase + mt * 16 + ((g & 1) << 3) + (lid & 7);
                    uint32_t sw = SW(row * 128 + kt * 32 + ((g >> 1) << 4));
                    ldsm_x4(a_hi[mt][kt][0], a_hi[mt][kt][1], a_hi[mt][kt][2], a_hi[mt][kt][3],
                            sbase + SM_AHI + sw);
                    ldsm_x4(a_lo[mt][kt][0], a_lo[mt][kt][1], a_lo[mt][kt][2], a_lo[mt][kt][3],
                            sbase + SM_ALO + sw);
                }
        }

        // ---------- main loop: 32 n-tile pairs; batch ALL 8 B-ldsm per ntp ----------
        float m1[4] = {-3.4e38f, -3.4e38f, -3.4e38f, -3.4e38f};
        int   i1[4] = {0, 0, 0, 0};

        #pragma unroll 2
        for (int ntp = 0; ntp < 32; ntp++) {
            uint32_t B[4][8];
            #pragma unroll
            for (int kt = 0; kt < 4; kt++) {
                uint32_t sw = SW((uint32_t)((ntp * 16 + brow) * 128 + kt * 32 + bk_off));
                ldsm_x4(B[kt][0], B[kt][1], B[kt][2], B[kt][3], sbase + SM_BHI + sw);
                ldsm_x4(B[kt][4], B[kt][5], B[kt][6], B[kt][7], sbase + SM_BLO + sw);
            }
            float acc[2][2][4] = {{{0.f,0.f,0.f,0.f},{0.f,0.f,0.f,0.f}},
                                  {{0.f,0.f,0.f,0.f},{0.f,0.f,0.f,0.f}}};
            #pragma unroll
            for (int kt = 0; kt < 4; kt++) {
                #pragma unroll
                for (int mt = 0; mt < 2; mt++) {
                    mma16816(acc[0][mt], a_hi[mt][kt], B[kt][0], B[kt][1]);
                    mma16816(acc[1][mt], a_hi[mt][kt], B[kt][2], B[kt][3]);
                    mma16816(acc[0][mt], a_hi[mt][kt], B[kt][4], B[kt][5]);
                    mma16816(acc[1][mt], a_hi[mt][kt], B[kt][6], B[kt][7]);
                    mma16816(acc[0][mt], a_lo[mt][kt], B[kt][0], B[kt][1]);
                    mma16816(acc[1][mt], a_lo[mt][kt], B[kt][2], B[kt][3]);
                }
            }
            #pragma unroll
            for (int h = 0; h < 2; h++)
                #pragma unroll
                for (int mt = 0; mt < 2; mt++)
                    #pragma unroll
                    for (int i = 0; i < 4; i++) {
                        int s = mt * 2 + (i >> 1);
                        int k = ntp * 16 + h * 8 + 2 * (lid & 3) + (i & 1);
                        float dot = acc[h][mt][i];
                        if (dot > m1[s]) { m1[s] = dot; i1[s] = k; }
                    }
        }

        // ---------- issue next tile's z LDGs (overlap with epilogue) ----------
        {
            int ntile = tile + GRID;
            if (ntile >= NTILES) ntile = tile;       // dummy valid address
            const int nn = ntile * CTA_M + tid;
            const int nb = nn >> 12, nr = nn & 4095;
            const float* znp = z_e + (size_t)nb * (DIMS * HT) + nr;
            #pragma unroll
            for (int d = 0; d < 32; d++) {
                zraw[d]  = __ldg(znp + (size_t)(2 * d) * HT);
                zraw2[d] = __ldg(znp + (size_t)(2 * d + 1) * HT);
            }
        }

        // ---------- merge max(dot) across the 4 quad lanes ----------
        #pragma unroll
        for (int off = 1; off <= 2; off <<= 1) {
            #pragma unroll
            for (int s = 0; s < 4; s++) {
                float om = __shfl_xor_sync(0xffffffffu, m1[s], off);
                int   oi = __shfl_xor_sync(0xffffffffu, i1[s], off);
                bool take = (om > m1[s]) || (om == m1[s] && oi < i1[s]);
                if (take) { m1[s] = om; i1[s] = oi; }
            }
        }
        // shuffle-based bi: row = tid lives in this warp; slot s + quad give source
        int bi;
        {
            const int src = 4 * (lid & 7);
            const int s   = ((lid >> 4) << 1) + ((lid >> 3) & 1);
            int v0 = __shfl_sync(0xffffffffu, i1[0], src);
            int v1 = __shfl_sync(0xffffffffu, i1[1], src);
            int v2 = __shfl_sync(0xffffffffu, i1[2], src);
            int v3 = __shfl_sync(0xffffffffu, i1[3], src);
            bi = (s == 0) ? v0 : (s == 1) ? v1 : (s == 2) ? v2 : v3;
        }

        // ---------- outputs (row = tid) ----------
        float* op = out + (size_t)b * (DIMS * HT) + r;
        float csum = 0.f;
        #pragma unroll
        for (int dg = 0; dg < 16; dg++) {
            uint32_t zo = SW(tid * 128 + dg * 8);
            uint2 zh = *(uint2*)(smem + SM_AHI + zo);
            uint2 zl = *(uint2*)(smem + SM_ALO + zo);
            float2 z01 = u2f(zh.x), zl01 = u2f(zl.x), z23 = u2f(zh.y), zl23 = u2f(zl.y);
            float zv0 = z01.x + zl01.x, zv1 = z01.y + zl01.y;
            float zv2 = z23.x + zl23.x, zv3 = z23.y + zl23.y;
            uint32_t qo = SW(bi * 128 + dg * 8);
            uint2 qh = *(uint2*)(smem + SM_BHI + qo);
            uint2 ql = *(uint2*)(smem + SM_BLO + qo);
            float2 e01 = u2f(qh.x), el01 = u2f(ql.x), e23 = u2f(qh.y), el23 = u2f(ql.y);
            float q0 = e01.x + el01.x, q1 = e01.y + el01.y, q2 = e23.x + el23.x, q3 = e23.y + el23.y;
            float d0 = q0 - zv0, d1v = q1 - zv1, d2v = q2 - zv2, d3 = q3 - zv3;
            op[(4 * dg + 0) * HT] = zv0 + d0;
            op[(4 * dg + 1) * HT] = zv1 + d1v;
            op[(4 * dg + 2) * HT] = zv2 + d2v;
            op[(4 * dg + 3) * HT] = zv3 + d3;
            csum += d0 * d0 + d1v * d1v + d2v * d2v + d3 * d3;
        }
        out[ZQ_SIZE + 1 + n] = (float)bi;
        atomicAdd(&g_counts[bi], 1);
        csum_total += csum;

        __syncthreads();   // protect A smem before next tile's A-fill
    }

    // ---------- per-CTA commitment partial ----------
    #pragma unroll
    for (int off = 16; off; off >>= 1)
        csum_total += __shfl_down_sync(0xffffffffu, csum_total, off);
    float* wsum = (float*)(smem + SM_WSUM);
    if (lid == 0) wsum[wid] = csum_total;
    __syncthreads();
    if (tid == 0) {
        float s = 0.f;
        #pragma unroll
        for (int w = 0; w < 8; w++) s += wsum[w];
        g_part[blockIdx.x] = s;
    }

    // ---------- last-CTA in-kernel finalize ----------
    __threadfence();
    __shared__ int s_last;
    if (tid == 0) s_last = (atomicAdd(&g_done, 1) == GRID - 1);
    __syncthreads();
    if (s_last) {
        __threadfence();
        float* red = (float*)(smem + SM_RED);

        // commitment
        red[tid] = (tid < GRID) ? g_part[tid] : 0.f;
        __syncthreads();
        #pragma unroll
        for (int off = 128; off; off >>= 1) {
            if (tid < off) red[tid] += red[tid + off];
            __syncthreads();
        }
        if (tid == 0) out[ZQ_SIZE] = 0.25f * red[0] / (float)ZQ_SIZE;
        __syncthreads();

        // entropy -> perplexity (512 codes, 2 per thread)
        const int c0 = g_counts[tid], c1 = g_counts[tid + 256];
        {
            float p0 = (float)c0 / (float)N_VEC, p1 = (float)c1 / (float)N_VEC;
            red[tid] = -p0 * logf(p0 + 1e-12f) - p1 * logf(p1 + 1e-12f);
        }
        __syncthreads();
        #pragma unroll
        for (int off = 128; off; off >>= 1) {
            if (tid < off) red[tid] += red[tid + off];
            __syncthreads();
        }
        if (tid == 0) out[ZQ_SIZE + 1 + N_VEC] = expf(red[0]);
        __syncthreads();

        // usage
        red[tid] = ((c0 > 0) ? 1.f : 0.f) + ((c1 > 0) ? 1.f : 0.f);
        __syncthreads();
        #pragma unroll
        for (int off = 128; off; off >>= 1) {
            if (tid < off) red[tid] += red[tid + off];
            __syncthreads();
        }
        if (tid == 0) out[ZQ_SIZE + 1 + N_VEC + 1] = red[0] / (float)NUM_CODES;

        // reset state for next graph replay
        g_counts[tid] = 0;
        g_counts[tid + 256] = 0;
        if (tid == 0) g_done = 0;
    }
}

extern "C" void kernel_launch(void* const* d_in, const int* in_sizes, int n_in,
                              void* d_out, int out_size) {
    const float* z_e   = (const float*)d_in[0];
    const float* embed = (const float*)d_in[1];
    float* out = (float*)d_out;

    cudaFuncSetAttribute(vq_main, cudaFuncAttributeMaxDynamicSharedMemorySize, SMEM_TOTAL);
    vq_main<<<GRID, THREADS, SMEM_TOTAL>>>(z_e, embed, out);
}

// round 12
// speedup vs baseline: 1.0861x; 1.0280x over previous
#include <cuda_runtime.h>
#include <cuda_fp16.h>
#include <cstdint>

#define NUM_CODES 512
#define DIMS      64
#define HT        4096
#define N_VEC     131072
#define ZQ_SIZE   8388608
#define CTA_M     256
#define THREADS   256
#define GRID      148
#define NTILES    512

// ---- dynamic smem layout (bytes), MMA regions 1024-aligned for SW128 ----
#define SM_AHI   0
#define SM_ALO   32768
#define SM_BHI   65536
#define SM_BLO   131072
#define SM_WSUM  196608
#define SM_RED   196672          // 512 floats for in-kernel finalize
#define SMEM_TOTAL 198720

__device__ float g_part[GRID];        // zero-init; overwritten every call
__device__ int   g_counts[NUM_CODES]; // zero-init; reset by finalize branch
__device__ int   g_done;              // zero-init; reset by finalize branch

#define SW(x) ((x) ^ ((((uint32_t)(x)) >> 3) & 0x70))

__device__ __forceinline__ uint32_t smem_u32(const void* p) {
    uint32_t a;
    asm("{ .reg .u64 t; cvta.to.shared.u64 t, %1; cvt.u32.u64 %0, t; }" : "=r"(a) : "l"(p));
    return a;
}
__device__ __forceinline__ void ldsm_x4(uint32_t& r0, uint32_t& r1, uint32_t& r2, uint32_t& r3, uint32_t a) {
    asm volatile("ldmatrix.sync.aligned.m8n8.x4.shared.b16 {%0,%1,%2,%3}, [%4];"
                 : "=r"(r0), "=r"(r1), "=r"(r2), "=r"(r3) : "r"(a));
}
__device__ __forceinline__ void mma16816(float* c, const uint32_t* a, uint32_t b0, uint32_t b1) {
    asm volatile("mma.sync.aligned.m16n8k16.row.col.f32.f16.f16.f32 "
                 "{%0,%1,%2,%3}, {%4,%5,%6,%7}, {%8,%9}, {%0,%1,%2,%3};"
                 : "+f"(c[0]), "+f"(c[1]), "+f"(c[2]), "+f"(c[3])
                 : "r"(a[0]), "r"(a[1]), "r"(a[2]), "r"(a[3]), "r"(b0), "r"(b1));
}
__device__ __forceinline__ uint32_t h2u(__half2 h) { return reinterpret_cast<uint32_t&>(h); }
__device__ __forceinline__ float2   u2f(uint32_t u) { __half2 h = reinterpret_cast<__half2&>(u); return __half22float2(h); }

__global__ __launch_bounds__(THREADS, 1) void vq_main(
    const float* __restrict__ z_e, const float* __restrict__ embed,
    float* __restrict__ out)
{
    extern __shared__ char smem[];
    const uint32_t sbase = smem_u32(smem);
    const int tid = threadIdx.x, wid = tid >> 5, lid = tid & 31;

    // ---------- B fill ONCE: embedding (512x64 fp32) -> f16 hi/lo, SW128 ----------
    {
        const float4* e4 = (const float4*)embed;
        #pragma unroll 8
        for (int i = tid; i < NUM_CODES * DIMS / 4; i += THREADS) {
            float4 f = e4[i];
            int row = i >> 4, dg = i & 15;
            __half hx = __float2half_rn(f.x), hy = __float2half_rn(f.y);
            __half hz = __float2half_rn(f.z), hw = __float2half_rn(f.w);
            __half lx = __float2half_rn(f.x - __half2float(hx));
            __half ly = __float2half_rn(f.y - __half2float(hy));
            __half lz = __float2half_rn(f.z - __half2float(hz));
            __half lw = __float2half_rn(f.w - __half2float(hw));
            uint32_t off = SW(row * 128 + dg * 8);
            *(uint2*)(smem + SM_BHI + off) = make_uint2(h2u(__halves2half2(hx, hy)), h2u(__halves2half2(hz, hw)));
            *(uint2*)(smem + SM_BLO + off) = make_uint2(h2u(__halves2half2(lx, ly)), h2u(__halves2half2(lz, lw)));
        }
    }

    const int rbase = wid * 32;
    const uint32_t brow = ((lid >> 4) << 3) + (lid & 7);
    const uint32_t bk_off = ((lid >> 3) & 1) << 4;
    const int kb = 2 * (lid & 3);
    float csum_total = 0.f;

    // ---------- prefetch first tile's z into registers ----------
    float zraw[32], zraw2[32];
    {
        const int n0 = blockIdx.x * CTA_M + tid;
        const int b0 = n0 >> 12, r0 = n0 & 4095;
        const float* zp0 = z_e + (size_t)b0 * (DIMS * HT) + r0;
        #pragma unroll
        for (int d = 0; d < 32; d++) {
            zraw[d]  = zp0[(size_t)(2 * d) * HT];
            zraw2[d] = zp0[(size_t)(2 * d + 1) * HT];
        }
    }

    // ================= persistent tile loop =================
    for (int tile = blockIdx.x; tile < NTILES; tile += GRID) {
        const int n = tile * CTA_M + tid;
        const int b = n >> 12, r = n & 4095;

        // ---------- A fill from registers -> f16 hi/lo, SW128 ----------
        #pragma unroll
        for (int i = 0; i < 8; i++) {
            uint32_t zh[4], zl[4];
            #pragma unroll
            for (int j = 0; j < 4; j++) {
                float x0 = zraw[4 * i + j];
                float x1 = zraw2[4 * i + j];
                __half h0 = __float2half_rn(x0), h1 = __float2half_rn(x1);
                __half l0 = __float2half_rn(x0 - __half2float(h0));
                __half l1 = __float2half_rn(x1 - __half2float(h1));
                zh[j] = h2u(__halves2half2(h0, h1));
                zl[j] = h2u(__halves2half2(l0, l1));
            }
            uint32_t off = SW(tid * 128 + i * 16);
            *(uint4*)(smem + SM_AHI + off) = make_uint4(zh[0], zh[1], zh[2], zh[3]);
            *(uint4*)(smem + SM_ALO + off) = make_uint4(zl[0], zl[1], zl[2], zl[3]);
        }
        __syncthreads();   // A (and on iter 0, B) ready

        // ---------- A fragments (2 m-tiles per warp) ----------
        uint32_t a_hi[2][4][4], a_lo[2][4][4];
        {
            const int g = lid >> 3;
            #pragma unroll
            for (int mt = 0; mt < 2; mt++)
                #pragma unroll
                for (int kt = 0; kt < 4; kt++) {
                    uint32_t row = rbase + mt * 16 + ((g & 1) << 3) + (lid & 7);
                    uint32_t sw = SW(row * 128 + kt * 32 + ((g >> 1) << 4));
                    ldsm_x4(a_hi[mt][kt][0], a_hi[mt][kt][1], a_hi[mt][kt][2], a_hi[mt][kt][3],
                            sbase + SM_AHI + sw);
                    ldsm_x4(a_lo[mt][kt][0], a_lo[mt][kt][1], a_lo[mt][kt][2], a_lo[mt][kt][3],
                            sbase + SM_ALO + sw);
                }
        }

        // ---------- main loop: double-buffered accumulators ----------
        float m1[4] = {-3.4e38f, -3.4e38f, -3.4e38f, -3.4e38f};
        int   i1[4] = {0, 0, 0, 0};
        float acc0[2][2][4], acc1[2][2][4];

#define ZEROACC(A)                                                                 \
        { _Pragma("unroll") for (int h = 0; h < 2; h++)                            \
          _Pragma("unroll") for (int mt = 0; mt < 2; mt++)                         \
          _Pragma("unroll") for (int i = 0; i < 4; i++) (A)[h][mt][i] = 0.f; }

#define DOMMA(A, NTP)                                                              \
        { uint32_t B[4][8];                                                        \
          _Pragma("unroll")                                                        \
          for (int kt = 0; kt < 4; kt++) {                                         \
              uint32_t sw = SW((uint32_t)(((NTP) * 16 + brow) * 128 + kt * 32 + bk_off)); \
              ldsm_x4(B[kt][0], B[kt][1], B[kt][2], B[kt][3], sbase + SM_BHI + sw);\
              ldsm_x4(B[kt][4], B[kt][5], B[kt][6], B[kt][7], sbase + SM_BLO + sw);\
          }                                                                        \
          _Pragma("unroll")                                                        \
          for (int kt = 0; kt < 4; kt++) {                                         \
              _Pragma("unroll")                                                    \
              for (int mt = 0; mt < 2; mt++) {                                     \
                  mma16816((A)[0][mt], a_hi[mt][kt], B[kt][0], B[kt][1]);          \
                  mma16816((A)[1][mt], a_hi[mt][kt], B[kt][2], B[kt][3]);          \
                  mma16816((A)[0][mt], a_hi[mt][kt], B[kt][4], B[kt][5]);          \
                  mma16816((A)[1][mt], a_hi[mt][kt], B[kt][6], B[kt][7]);          \
                  mma16816((A)[0][mt], a_lo[mt][kt], B[kt][0], B[kt][1]);          \
                  mma16816((A)[1][mt], a_lo[mt][kt], B[kt][2], B[kt][3]);          \
              }                                                                    \
          } }

#define TRACK(A, NTP)                                                              \
        { const int kbase = (NTP) * 16 + kb;                                       \
          _Pragma("unroll") for (int h = 0; h < 2; h++)                            \
          _Pragma("unroll") for (int mt = 0; mt < 2; mt++)                         \
          _Pragma("unroll") for (int i = 0; i < 4; i++) {                          \
              int s = mt * 2 + (i >> 1);                                           \
              int k = kbase + h * 8 + (i & 1);                                     \
              float dot = (A)[h][mt][i];                                           \
              if (dot > m1[s]) { m1[s] = dot; i1[s] = k; }                         \
          } }

        // pipelined: issue MMAs for ntp, then track ntp-1 (other buffer)
        ZEROACC(acc0);
        DOMMA(acc0, 0);
        #pragma unroll 2
        for (int ntpp = 0; ntpp < 15; ntpp++) {
            const int e = 2 * ntpp;
            ZEROACC(acc1);
            DOMMA(acc1, e + 1);
            TRACK(acc0, e);
            ZEROACC(acc0);
            DOMMA(acc0, e + 2);
            TRACK(acc1, e + 1);
        }
        ZEROACC(acc1);
        DOMMA(acc1, 31);
        TRACK(acc0, 30);
        TRACK(acc1, 31);

        // ---------- issue next tile's z LDGs (overlap with epilogue) ----------
        {
            int ntile = tile + GRID;
            if (ntile >= NTILES) ntile = tile;       // dummy valid address
            const int nn = ntile * CTA_M + tid;
            const int nb = nn >> 12, nr = nn & 4095;
            const float* znp = z_e + (size_t)nb * (DIMS * HT) + nr;
            #pragma unroll
            for (int d = 0; d < 32; d++) {
                zraw[d]  = __ldg(znp + (size_t)(2 * d) * HT);
                zraw2[d] = __ldg(znp + (size_t)(2 * d + 1) * HT);
            }
        }

        // ---------- merge max(dot) across the 4 quad lanes ----------
        #pragma unroll
        for (int off = 1; off <= 2; off <<= 1) {
            #pragma unroll
            for (int s = 0; s < 4; s++) {
                float om = __shfl_xor_sync(0xffffffffu, m1[s], off);
                int   oi = __shfl_xor_sync(0xffffffffu, i1[s], off);
                bool take = (om > m1[s]) || (om == m1[s] && oi < i1[s]);
                if (take) { m1[s] = om; i1[s] = oi; }
            }
        }
        // shuffle-based bi: row = tid lives in this warp; slot s + quad give source
        int bi;
        {
            const int src = 4 * (lid & 7);
            const int s   = ((lid >> 4) << 1) + ((lid >> 3) & 1);
            int v0 = __shfl_sync(0xffffffffu, i1[0], src);
            int v1 = __shfl_sync(0xffffffffu, i1[1], src);
            int v2 = __shfl_sync(0xffffffffu, i1[2], src);
            int v3 = __shfl_sync(0xffffffffu, i1[3], src);
            bi = (s == 0) ? v0 : (s == 1) ? v1 : (s == 2) ? v2 : v3;
        }

        // ---------- outputs (row = tid) ----------
        float* op = out + (size_t)b * (DIMS * HT) + r;
        float csum = 0.f;
        #pragma unroll
        for (int dg = 0; dg < 16; dg++) {
            uint32_t zo = SW(tid * 128 + dg * 8);
            uint2 zh = *(uint2*)(smem + SM_AHI + zo);
            uint2 zl = *(uint2*)(smem + SM_ALO + zo);
            float2 z01 = u2f(zh.x), zl01 = u2f(zl.x), z23 = u2f(zh.y), zl23 = u2f(zl.y);
            float zv0 = z01.x + zl01.x, zv1 = z01.y + zl01.y;
            float zv2 = z23.x + zl23.x, zv3 = z23.y + zl23.y;
            uint32_t qo = SW(bi * 128 + dg * 8);
            uint2 qh = *(uint2*)(smem + SM_BHI + qo);
            uint2 ql = *(uint2*)(smem + SM_BLO + qo);
            float2 e01 = u2f(qh.x), el01 = u2f(ql.x), e23 = u2f(qh.y), el23 = u2f(ql.y);
            float q0 = e01.x + el01.x, q1 = e01.y + el01.y, q2 = e23.x + el23.x, q3 = e23.y + el23.y;
            float d0 = q0 - zv0, d1v = q1 - zv1, d2v = q2 - zv2, d3 = q3 - zv3;
            op[(4 * dg + 0) * HT] = zv0 + d0;
            op[(4 * dg + 1) * HT] = zv1 + d1v;
            op[(4 * dg + 2) * HT] = zv2 + d2v;
            op[(4 * dg + 3) * HT] = zv3 + d3;
            csum += d0 * d0 + d1v * d1v + d2v * d2v + d3 * d3;
        }
        out[ZQ_SIZE + 1 + n] = (float)bi;
        atomicAdd(&g_counts[bi], 1);
        csum_total += csum;

        __syncthreads();   // protect A smem before next tile's A-fill
    }

    // ---------- per-CTA commitment partial ----------
    #pragma unroll
    for (int off = 16; off; off >>= 1)
        csum_total += __shfl_down_sync(0xffffffffu, csum_total, off);
    float* wsum = (float*)(smem + SM_WSUM);
    if (lid == 0) wsum[wid] = csum_total;
    __syncthreads();
    if (tid == 0) {
        float s = 0.f;
        #pragma unroll
        for (int w = 0; w < 8; w++) s += wsum[w];
        g_part[blockIdx.x] = s;
    }

    // ---------- last-CTA in-kernel finalize ----------
    __threadfence();
    __shared__ int s_last;
    if (tid == 0) s_last = (atomicAdd(&g_done, 1) == GRID - 1);
    __syncthreads();
    if (s_last) {
        __threadfence();
        float* red = (float*)(smem + SM_RED);

        // commitment
        red[tid] = (tid < GRID) ? g_part[tid] : 0.f;
        __syncthreads();
        #pragma unroll
        for (int off = 128; off; off >>= 1) {
            if (tid < off) red[tid] += red[tid + off];
            __syncthreads();
        }
        if (tid == 0) out[ZQ_SIZE] = 0.25f * red[0] / (float)ZQ_SIZE;
        __syncthreads();

        // entropy -> perplexity (512 codes, 2 per thread)
        const int c0 = g_counts[tid], c1 = g_counts[tid + 256];
        {
            float p0 = (float)c0 / (float)N_VEC, p1 = (float)c1 / (float)N_VEC;
            red[tid] = -p0 * logf(p0 + 1e-12f) - p1 * logf(p1 + 1e-12f);
        }
        __syncthreads();
        #pragma unroll
        for (int off = 128; off; off >>= 1) {
            if (tid < off) red[tid] += red[tid + off];
            __syncthreads();
        }
        if (tid == 0) out[ZQ_SIZE + 1 + N_VEC] = expf(red[0]);
        __syncthreads();

        // usage
        red[tid] = ((c0 > 0) ? 1.f : 0.f) + ((c1 > 0) ? 1.f : 0.f);
        __syncthreads();
        #pragma unroll
        for (int off = 128; off; off >>= 1) {
            if (tid < off) red[tid] += red[tid + off];
            __syncthreads();
        }
        if (tid == 0) out[ZQ_SIZE + 1 + N_VEC + 1] = red[0] / (float)NUM_CODES;

        // reset state for next graph replay
        g_counts[tid] = 0;
        g_counts[tid + 256] = 0;
        if (tid == 0) g_done = 0;
    }
}

extern "C" void kernel_launch(void* const* d_in, const int* in_sizes, int n_in,
                              void* d_out, int out_size) {
    const float* z_e   = (const float*)d_in[0];
    const float* embed = (const float*)d_in[1];
    float* out = (float*)d_out;

    cudaFuncSetAttribute(vq_main, cudaFuncAttributeMaxDynamicSharedMemorySize, SMEM_TOTAL);
    vq_main<<<GRID, THREADS, SMEM_TOTAL>>>(z_e, embed, out);
}

// round 13
// speedup vs baseline: 1.0868x; 1.0007x over previous
#include <cuda_runtime.h>
#include <cuda_fp16.h>
#include <cstdint>

#define NUM_CODES 512
#define DIMS      64
#define HT        4096
#define N_VEC     131072
#define ZQ_SIZE   8388608
#define CTA_M     256
#define THREADS   256
#define GRID      148
#define NTILES    512

// ---- dynamic smem layout (bytes), MMA regions 1024-aligned for SW128 ----
#define SM_AHI   0
#define SM_ALO   32768
#define SM_BHI   65536
#define SM_BLO   131072
#define SM_WSUM  196608
#define SM_RED   196672          // 512 floats for in-kernel finalize
#define SMEM_TOTAL 198720

__device__ float g_part[GRID];        // zero-init; overwritten every call
__device__ int   g_counts[NUM_CODES]; // zero-init; reset by finalize branch
__device__ int   g_done;              // zero-init; reset by finalize branch

#define SW(x) ((x) ^ ((((uint32_t)(x)) >> 3) & 0x70))

__device__ __forceinline__ uint32_t smem_u32(const void* p) {
    uint32_t a;
    asm("{ .reg .u64 t; cvta.to.shared.u64 t, %1; cvt.u32.u64 %0, t; }" : "=r"(a) : "l"(p));
    return a;
}
__device__ __forceinline__ void ldsm_x4(uint32_t& r0, uint32_t& r1, uint32_t& r2, uint32_t& r3, uint32_t a) {
    asm volatile("ldmatrix.sync.aligned.m8n8.x4.shared.b16 {%0,%1,%2,%3}, [%4];"
                 : "=r"(r0), "=r"(r1), "=r"(r2), "=r"(r3) : "r"(a));
}
__device__ __forceinline__ void mma16816(float* c, const uint32_t* a, uint32_t b0, uint32_t b1) {
    asm volatile("mma.sync.aligned.m16n8k16.row.col.f32.f16.f16.f32 "
                 "{%0,%1,%2,%3}, {%4,%5,%6,%7}, {%8,%9}, {%0,%1,%2,%3};"
                 : "+f"(c[0]), "+f"(c[1]), "+f"(c[2]), "+f"(c[3])
                 : "r"(a[0]), "r"(a[1]), "r"(a[2]), "r"(a[3]), "r"(b0), "r"(b1));
}
__device__ __forceinline__ uint32_t h2u(__half2 h) { return reinterpret_cast<uint32_t&>(h); }
__device__ __forceinline__ float2   u2f(uint32_t u) { __half2 h = reinterpret_cast<__half2&>(u); return __half22float2(h); }

__global__ __launch_bounds__(THREADS, 1) void vq_main(
    const float* __restrict__ z_e, const float* __restrict__ embed,
    float* __restrict__ out)
{
    extern __shared__ char smem[];
    const uint32_t sbase = smem_u32(smem);
    const int tid = threadIdx.x, wid = tid >> 5, lid = tid & 31;

    // ---------- B fill ONCE: embedding (512x64 fp32) -> f16 hi/lo, SW128 ----------
    {
        const float4* e4 = (const float4*)embed;
        #pragma unroll 8
        for (int i = tid; i < NUM_CODES * DIMS / 4; i += THREADS) {
            float4 f = e4[i];
            int row = i >> 4, dg = i & 15;
            __half hx = __float2half_rn(f.x), hy = __float2half_rn(f.y);
            __half hz = __float2half_rn(f.z), hw = __float2half_rn(f.w);
            __half lx = __float2half_rn(f.x - __half2float(hx));
            __half ly = __float2half_rn(f.y - __half2float(hy));
            __half lz = __float2half_rn(f.z - __half2float(hz));
            __half lw = __float2half_rn(f.w - __half2float(hw));
            uint32_t off = SW(row * 128 + dg * 8);
            *(uint2*)(smem + SM_BHI + off) = make_uint2(h2u(__halves2half2(hx, hy)), h2u(__halves2half2(hz, hw)));
            *(uint2*)(smem + SM_BLO + off) = make_uint2(h2u(__halves2half2(lx, ly)), h2u(__halves2half2(lz, lw)));
        }
    }

    const int rbase = wid * 32;
    const uint32_t brow = ((lid >> 4) << 3) + (lid & 7);
    const uint32_t bk_off = ((lid >> 3) & 1) << 4;
    const int kb = 2 * (lid & 3);
    float csum_total = 0.f;

    // ---------- prefetch first tile's z into registers ----------
    float zraw[32], zraw2[32];
    {
        const int n0 = blockIdx.x * CTA_M + tid;
        const int b0 = n0 >> 12, r0 = n0 & 4095;
        const float* zp0 = z_e + (size_t)b0 * (DIMS * HT) + r0;
        #pragma unroll
        for (int d = 0; d < 32; d++) {
            zraw[d]  = zp0[(size_t)(2 * d) * HT];
            zraw2[d] = zp0[(size_t)(2 * d + 1) * HT];
        }
    }

    // ================= persistent tile loop =================
    for (int tile = blockIdx.x; tile < NTILES; tile += GRID) {
        const int n = tile * CTA_M + tid;
        const int b = n >> 12, r = n & 4095;

        // ---------- A fill from registers -> f16 hi/lo, SW128 ----------
        #pragma unroll
        for (int i = 0; i < 8; i++) {
            uint32_t zh[4], zl[4];
            #pragma unroll
            for (int j = 0; j < 4; j++) {
                float x0 = zraw[4 * i + j];
                float x1 = zraw2[4 * i + j];
                __half h0 = __float2half_rn(x0), h1 = __float2half_rn(x1);
                __half l0 = __float2half_rn(x0 - __half2float(h0));
                __half l1 = __float2half_rn(x1 - __half2float(h1));
                zh[j] = h2u(__halves2half2(h0, h1));
                zl[j] = h2u(__halves2half2(l0, l1));
            }
            uint32_t off = SW(tid * 128 + i * 16);
            *(uint4*)(smem + SM_AHI + off) = make_uint4(zh[0], zh[1], zh[2], zh[3]);
            *(uint4*)(smem + SM_ALO + off) = make_uint4(zl[0], zl[1], zl[2], zl[3]);
        }
        __syncthreads();   // A (and on iter 0, B) ready

        // ---------- A fragments (2 m-tiles per warp) ----------
        uint32_t a_hi[2][4][4], a_lo[2][4][4];
        {
            const int g = lid >> 3;
            #pragma unroll
            for (int mt = 0; mt < 2; mt++)
                #pragma unroll
                for (int kt = 0; kt < 4; kt++) {
                    uint32_t row = rbase + mt * 16 + ((g & 1) << 3) + (lid & 7);
                    uint32_t sw = SW(row * 128 + kt * 32 + ((g >> 1) << 4));
                    ldsm_x4(a_hi[mt][kt][0], a_hi[mt][kt][1], a_hi[mt][kt][2], a_hi[mt][kt][3],
                            sbase + SM_AHI + sw);
                    ldsm_x4(a_lo[mt][kt][0], a_lo[mt][kt][1], a_lo[mt][kt][2], a_lo[mt][kt][3],
                            sbase + SM_ALO + sw);
                }
        }

        // ---------- main loop: double-buffered accumulators ----------
        float m1[4] = {-3.4e38f, -3.4e38f, -3.4e38f, -3.4e38f};
        int   i1[4] = {0, 0, 0, 0};
        float acc0[2][2][4], acc1[2][2][4];

#define ZEROACC(A)                                                                 \
        { _Pragma("unroll") for (int h = 0; h < 2; h++)                            \
          _Pragma("unroll") for (int mt = 0; mt < 2; mt++)                         \
          _Pragma("unroll") for (int i = 0; i < 4; i++) (A)[h][mt][i] = 0.f; }

        // round-robin over all 4 accumulators: same-acc stride = 4 MMAs
        // (per-acc operand order unchanged vs R12 -> bit-identical results)
#define DOMMA(A, NTP)                                                              \
        { uint32_t B[4][8];                                                        \
          _Pragma("unroll")                                                        \
          for (int kt = 0; kt < 4; kt++) {                                         \
              uint32_t sw = SW((uint32_t)(((NTP) * 16 + brow) * 128 + kt * 32 + bk_off)); \
              ldsm_x4(B[kt][0], B[kt][1], B[kt][2], B[kt][3], sbase + SM_BHI + sw);\
              ldsm_x4(B[kt][4], B[kt][5], B[kt][6], B[kt][7], sbase + SM_BLO + sw);\
          }                                                                        \
          _Pragma("unroll")                                                        \
          for (int kt = 0; kt < 4; kt++) {                                         \
              mma16816((A)[0][0], a_hi[0][kt], B[kt][0], B[kt][1]);                \
              mma16816((A)[1][0], a_hi[0][kt], B[kt][2], B[kt][3]);                \
              mma16816((A)[0][1], a_hi[1][kt], B[kt][0], B[kt][1]);                \
              mma16816((A)[1][1], a_hi[1][kt], B[kt][2], B[kt][3]);                \
              mma16816((A)[0][0], a_hi[0][kt], B[kt][4], B[kt][5]);                \
              mma16816((A)[1][0], a_hi[0][kt], B[kt][6], B[kt][7]);                \
              mma16816((A)[0][1], a_hi[1][kt], B[kt][4], B[kt][5]);                \
              mma16816((A)[1][1], a_hi[1][kt], B[kt][6], B[kt][7]);                \
              mma16816((A)[0][0], a_lo[0][kt], B[kt][0], B[kt][1]);                \
              mma16816((A)[1][0], a_lo[0][kt], B[kt][2], B[kt][3]);                \
              mma16816((A)[0][1], a_lo[1][kt], B[kt][0], B[kt][1]);                \
              mma16816((A)[1][1], a_lo[1][kt], B[kt][2], B[kt][3]);                \
          } }

#define TRACK(A, NTP)                                                              \
        { const int kbase = (NTP) * 16 + kb;                                       \
          _Pragma("unroll") for (int h = 0; h < 2; h++)                            \
          _Pragma("unroll") for (int mt = 0; mt < 2; mt++)                         \
          _Pragma("unroll") for (int i = 0; i < 4; i++) {                          \
              int s = mt * 2 + (i >> 1);                                           \
              int k = kbase + h * 8 + (i & 1);                                     \
              float dot = (A)[h][mt][i];                                           \
              if (dot > m1[s]) { m1[s] = dot; i1[s] = k; }                         \
          } }

        // pipelined: issue MMAs for ntp, then track ntp-1 (other buffer)
        ZEROACC(acc0);
        DOMMA(acc0, 0);
        #pragma unroll 2
        for (int ntpp = 0; ntpp < 15; ntpp++) {
            const int e = 2 * ntpp;
            ZEROACC(acc1);
            DOMMA(acc1, e + 1);
            TRACK(acc0, e);
            ZEROACC(acc0);
            DOMMA(acc0, e + 2);
            TRACK(acc1, e + 1);
        }
        ZEROACC(acc1);
        DOMMA(acc1, 31);
        TRACK(acc0, 30);
        TRACK(acc1, 31);

        // ---------- issue next tile's z LDGs (overlap with epilogue) ----------
        {
            int ntile = tile + GRID;
            if (ntile >= NTILES) ntile = tile;       // dummy valid address
            const int nn = ntile * CTA_M + tid;
            const int nb = nn >> 12, nr = nn & 4095;
            const float* znp = z_e + (size_t)nb * (DIMS * HT) + nr;
            #pragma unroll
            for (int d = 0; d < 32; d++) {
                zraw[d]  = __ldg(znp + (size_t)(2 * d) * HT);
                zraw2[d] = __ldg(znp + (size_t)(2 * d + 1) * HT);
            }
        }

        // ---------- merge max(dot) across the 4 quad lanes ----------
        #pragma unroll
        for (int off = 1; off <= 2; off <<= 1) {
            #pragma unroll
            for (int s = 0; s < 4; s++) {
                float om = __shfl_xor_sync(0xffffffffu, m1[s], off);
                int   oi = __shfl_xor_sync(0xffffffffu, i1[s], off);
                bool take = (om > m1[s]) || (om == m1[s] && oi < i1[s]);
                if (take) { m1[s] = om; i1[s] = oi; }
            }
        }
        // shuffle-based bi: row = tid lives in this warp; slot s + quad give source
        int bi;
        {
            const int src = 4 * (lid & 7);
            const int s   = ((lid >> 4) << 1) + ((lid >> 3) & 1);
            int v0 = __shfl_sync(0xffffffffu, i1[0], src);
            int v1 = __shfl_sync(0xffffffffu, i1[1], src);
            int v2 = __shfl_sync(0xffffffffu, i1[2], src);
            int v3 = __shfl_sync(0xffffffffu, i1[3], src);
            bi = (s == 0) ? v0 : (s == 1) ? v1 : (s == 2) ? v2 : v3;
        }

        // ---------- outputs (row = tid) ----------
        float* op = out + (size_t)b * (DIMS * HT) + r;
        float csum = 0.f;
        #pragma unroll
        for (int dg = 0; dg < 16; dg++) {
            uint32_t zo = SW(tid * 128 + dg * 8);
            uint2 zh = *(uint2*)(smem + SM_AHI + zo);
            uint2 zl = *(uint2*)(smem + SM_ALO + zo);
            float2 z01 = u2f(zh.x), zl01 = u2f(zl.x), z23 = u2f(zh.y), zl23 = u2f(zl.y);
            float zv0 = z01.x + zl01.x, zv1 = z01.y + zl01.y;
            float zv2 = z23.x + zl23.x, zv3 = z23.y + zl23.y;
            uint32_t qo = SW(bi * 128 + dg * 8);
            uint2 qh = *(uint2*)(smem + SM_BHI + qo);
            uint2 ql = *(uint2*)(smem + SM_BLO + qo);
            float2 e01 = u2f(qh.x), el01 = u2f(ql.x), e23 = u2f(qh.y), el23 = u2f(ql.y);
            float q0 = e01.x + el01.x, q1 = e01.y + el01.y, q2 = e23.x + el23.x, q3 = e23.y + el23.y;
            float d0 = q0 - zv0, d1v = q1 - zv1, d2v = q2 - zv2, d3 = q3 - zv3;
            op[(4 * dg + 0) * HT] = zv0 + d0;
            op[(4 * dg + 1) * HT] = zv1 + d1v;
            op[(4 * dg + 2) * HT] = zv2 + d2v;
            op[(4 * dg + 3) * HT] = zv3 + d3;
            csum += d0 * d0 + d1v * d1v + d2v * d2v + d3 * d3;
        }
        out[ZQ_SIZE + 1 + n] = (float)bi;
        atomicAdd(&g_counts[bi], 1);
        csum_total += csum;

        __syncthreads();   // protect A smem before next tile's A-fill
    }

    // ---------- per-CTA commitment partial ----------
    #pragma unroll
    for (int off = 16; off; off >>= 1)
        csum_total += __shfl_down_sync(0xffffffffu, csum_total, off);
    float* wsum = (float*)(smem + SM_WSUM);
    if (lid == 0) wsum[wid] = csum_total;
    __syncthreads();
    if (tid == 0) {
        float s = 0.f;
        #pragma unroll
        for (int w = 0; w < 8; w++) s += wsum[w];
        g_part[blockIdx.x] = s;
    }

    // ---------- last-CTA in-kernel finalize ----------
    __threadfence();
    __shared__ int s_last;
    if (tid == 0) s_last = (atomicAdd(&g_done, 1) == GRID - 1);
    __syncthreads();
    if (s_last) {
        __threadfence();
        float* red = (float*)(smem + SM_RED);

        // commitment
        red[tid] = (tid < GRID) ? g_part[tid] : 0.f;
        __syncthreads();
        #pragma unroll
        for (int off = 128; off; off >>= 1) {
            if (tid < off) red[tid] += red[tid + off];
            __syncthreads();
        }
        if (tid == 0) out[ZQ_SIZE] = 0.25f * red[0] / (float)ZQ_SIZE;
        __syncthreads();

        // entropy -> perplexity (512 codes, 2 per thread)
        const int c0 = g_counts[tid], c1 = g_counts[tid + 256];
        {
            float p0 = (float)c0 / (float)N_VEC, p1 = (float)c1 / (float)N_VEC;
            red[tid] = -p0 * logf(p0 + 1e-12f) - p1 * logf(p1 + 1e-12f);
        }
        __syncthreads();
        #pragma unroll
        for (int off = 128; off; off >>= 1) {
            if (tid < off) red[tid] += red[tid + off];
            __syncthreads();
        }
        if (tid == 0) out[ZQ_SIZE + 1 + N_VEC] = expf(red[0]);
        __syncthreads();

        // usage
        red[tid] = ((c0 > 0) ? 1.f : 0.f) + ((c1 > 0) ? 1.f : 0.f);
        __syncthreads();
        #pragma unroll
        for (int off = 128; off; off >>= 1) {
            if (tid < off) red[tid] += red[tid + off];
            __syncthreads();
        }
        if (tid == 0) out[ZQ_SIZE + 1 + N_VEC + 1] = red[0] / (float)NUM_CODES;

        // reset state for next graph replay
        g_counts[tid] = 0;
        g_counts[tid + 256] = 0;
        if (tid == 0) g_done = 0;
    }
}

extern "C" void kernel_launch(void* const* d_in, const int* in_sizes, int n_in,
                              void* d_out, int out_size) {
    const float* z_e   = (const float*)d_in[0];
    const float* embed = (const float*)d_in[1];
    float* out = (float*)d_out;

    cudaFuncSetAttribute(vq_main, cudaFuncAttributeMaxDynamicSharedMemorySize, SMEM_TOTAL);
    vq_main<<<GRID, THREADS, SMEM_TOTAL>>>(z_e, embed, out);
}

// round 14
// speedup vs baseline: 1.1670x; 1.0737x over previous
#include <cuda_runtime.h>
#include <cuda_fp16.h>
#include <cstdint>

#define NUM_CODES 512
#define DIMS      64
#define HT        4096
#define N_VEC     131072
#define ZQ_SIZE   8388608
#define CTA_M     128
#define THREADS   256
#define GRID      148
#define NTILES    1024

// ---- dynamic smem layout (bytes), MMA regions 1024-aligned for SW128 ----
#define SM_AHI   0
#define SM_ALO   16384
#define SM_BHI   32768
#define SM_BLO   98304
#define SM_WSUM  163840
#define SM_RED   163904          // 512 floats for in-kernel finalize
#define SMEM_TOTAL 165952

__device__ float g_part[GRID];        // zero-init; overwritten every call
__device__ int   g_counts[NUM_CODES]; // zero-init; reset by finalize branch
__device__ int   g_done;              // zero-init; reset by finalize branch

#define SW(x) ((x) ^ ((((uint32_t)(x)) >> 3) & 0x70))

__device__ __forceinline__ uint32_t smem_u32(const void* p) {
    uint32_t a;
    asm("{ .reg .u64 t; cvta.to.shared.u64 t, %1; cvt.u32.u64 %0, t; }" : "=r"(a) : "l"(p));
    return a;
}
__device__ __forceinline__ void ldsm_x4(uint32_t& r0, uint32_t& r1, uint32_t& r2, uint32_t& r3, uint32_t a) {
    asm volatile("ldmatrix.sync.aligned.m8n8.x4.shared.b16 {%0,%1,%2,%3}, [%4];"
                 : "=r"(r0), "=r"(r1), "=r"(r2), "=r"(r3) : "r"(a));
}
__device__ __forceinline__ void mma16816(float* c, const uint32_t* a, uint32_t b0, uint32_t b1) {
    asm volatile("mma.sync.aligned.m16n8k16.row.col.f32.f16.f16.f32 "
                 "{%0,%1,%2,%3}, {%4,%5,%6,%7}, {%8,%9}, {%0,%1,%2,%3};"
                 : "+f"(c[0]), "+f"(c[1]), "+f"(c[2]), "+f"(c[3])
                 : "r"(a[0]), "r"(a[1]), "r"(a[2]), "r"(a[3]), "r"(b0), "r"(b1));
}
__device__ __forceinline__ uint32_t h2u(__half2 h) { return reinterpret_cast<uint32_t&>(h); }
__device__ __forceinline__ float2   u2f(uint32_t u) { __half2 h = reinterpret_cast<__half2&>(u); return __half22float2(h); }

__global__ __launch_bounds__(THREADS, 1) void vq_main(
    const float* __restrict__ z_e, const float* __restrict__ embed,
    float* __restrict__ out)
{
    extern __shared__ char smem[];
    const uint32_t sbase = smem_u32(smem);
    const int tid = threadIdx.x, wid = tid >> 5, lid = tid & 31;

    // ---------- B fill ONCE: embedding (512x64 fp32) -> f16 hi/lo, SW128 ----------
    {
        const float4* e4 = (const float4*)embed;
        #pragma unroll 8
        for (int i = tid; i < NUM_CODES * DIMS / 4; i += THREADS) {
            float4 f = e4[i];
            int row = i >> 4, dg = i & 15;
            __half hx = __float2half_rn(f.x), hy = __float2half_rn(f.y);
            __half hz = __float2half_rn(f.z), hw = __float2half_rn(f.w);
            __half lx = __float2half_rn(f.x - __half2float(hx));
            __half ly = __float2half_rn(f.y - __half2float(hy));
            __half lz = __float2half_rn(f.z - __half2float(hz));
            __half lw = __float2half_rn(f.w - __half2float(hw));
            uint32_t off = SW(row * 128 + dg * 8);
            *(uint2*)(smem + SM_BHI + off) = make_uint2(h2u(__halves2half2(hx, hy)), h2u(__halves2half2(hz, hw)));
            *(uint2*)(smem + SM_BLO + off) = make_uint2(h2u(__halves2half2(lx, ly)), h2u(__halves2half2(lz, lw)));
        }
    }

    const int rbase = wid * 16;              // one m-tile (16 rows) per warp
    const int arow = tid >> 1;               // A-fill / epilogue: half row per thread
    const int ahalf = tid & 1;               // dims [ahalf*32, ahalf*32+32)
    const uint32_t brow = ((lid >> 4) << 3) + (lid & 7);
    const uint32_t bk_off = ((lid >> 3) & 1) << 4;
    const int kb = 2 * (lid & 3);
    float csum_total = 0.f;

    // ---------- prefetch first tile's z (half row) into registers ----------
    float zraw[16], zraw2[16];
    {
        const int n0 = blockIdx.x * CTA_M + arow;
        const int b0 = n0 >> 12, r0 = n0 & 4095;
        const float* zp0 = z_e + (size_t)b0 * (DIMS * HT) + r0 + (size_t)(ahalf * 32) * HT;
        #pragma unroll
        for (int d = 0; d < 16; d++) {
            zraw[d]  = zp0[(size_t)(2 * d) * HT];
            zraw2[d] = zp0[(size_t)(2 * d + 1) * HT];
        }
    }

    // ================= persistent tile loop =================
    for (int tile = blockIdx.x; tile < NTILES; tile += GRID) {
        const int n = tile * CTA_M + arow;
        const int b = n >> 12, r = n & 4095;

        // ---------- A fill from registers -> f16 hi/lo, SW128 ----------
        #pragma unroll
        for (int i = 0; i < 4; i++) {
            uint32_t zh[4], zl[4];
            #pragma unroll
            for (int j = 0; j < 4; j++) {
                float x0 = zraw[4 * i + j];
                float x1 = zraw2[4 * i + j];
                __half h0 = __float2half_rn(x0), h1 = __float2half_rn(x1);
                __half l0 = __float2half_rn(x0 - __half2float(h0));
                __half l1 = __float2half_rn(x1 - __half2float(h1));
                zh[j] = h2u(__halves2half2(h0, h1));
                zl[j] = h2u(__halves2half2(l0, l1));
            }
            uint32_t off = SW(arow * 128 + ahalf * 64 + i * 16);
            *(uint4*)(smem + SM_AHI + off) = make_uint4(zh[0], zh[1], zh[2], zh[3]);
            *(uint4*)(smem + SM_ALO + off) = make_uint4(zl[0], zl[1], zl[2], zl[3]);
        }
        __syncthreads();   // A (and on iter 0, B) ready

        // ---------- A fragments (1 m-tile per warp) ----------
        uint32_t a_hi[4][4], a_lo[4][4];
        {
            uint32_t row = rbase + ((lid >> 3) & 1) * 8 + (lid & 7);
            uint32_t cg  = (lid >> 4) << 4;
            #pragma unroll
            for (int kt = 0; kt < 4; kt++) {
                uint32_t sw = SW(row * 128 + kt * 32 + cg);
                ldsm_x4(a_hi[kt][0], a_hi[kt][1], a_hi[kt][2], a_hi[kt][3], sbase + SM_AHI + sw);
                ldsm_x4(a_lo[kt][0], a_lo[kt][1], a_lo[kt][2], a_lo[kt][3], sbase + SM_ALO + sw);
            }
        }

        // ---------- main loop: double-buffered accumulators ----------
        float m1[2] = {-3.4e38f, -3.4e38f};
        int   i1[2] = {0, 0};
        float acc0[2][4], acc1[2][4];

#define ZEROACC(A)                                                                 \
        { _Pragma("unroll") for (int h = 0; h < 2; h++)                            \
          _Pragma("unroll") for (int i = 0; i < 4; i++) (A)[h][i] = 0.f; }

#define DOMMA(A, NTP)                                                              \
        { uint32_t B[4][8];                                                        \
          _Pragma("unroll")                                                        \
          for (int kt = 0; kt < 4; kt++) {                                         \
              uint32_t sw = SW((uint32_t)(((NTP) * 16 + brow) * 128 + kt * 32 + bk_off)); \
              ldsm_x4(B[kt][0], B[kt][1], B[kt][2], B[kt][3], sbase + SM_BHI + sw);\
              ldsm_x4(B[kt][4], B[kt][5], B[kt][6], B[kt][7], sbase + SM_BLO + sw);\
          }                                                                        \
          _Pragma("unroll")                                                        \
          for (int kt = 0; kt < 4; kt++) {                                         \
              mma16816((A)[0], a_hi[kt], B[kt][0], B[kt][1]);                      \
              mma16816((A)[1], a_hi[kt], B[kt][2], B[kt][3]);                      \
              mma16816((A)[0], a_hi[kt], B[kt][4], B[kt][5]);                      \
              mma16816((A)[1], a_hi[kt], B[kt][6], B[kt][7]);                      \
              mma16816((A)[0], a_lo[kt], B[kt][0], B[kt][1]);                      \
              mma16816((A)[1], a_lo[kt], B[kt][2], B[kt][3]);                      \
          } }

#define TRACK(A, NTP)                                                              \
        { const int kbase = (NTP) * 16 + kb;                                       \
          _Pragma("unroll") for (int h = 0; h < 2; h++)                            \
          _Pragma("unroll") for (int i = 0; i < 4; i++) {                          \
              int s = i >> 1;                                                      \
              int k = kbase + h * 8 + (i & 1);                                     \
              float dot = (A)[h][i];                                               \
              if (dot > m1[s]) { m1[s] = dot; i1[s] = k; }                         \
          } }

        ZEROACC(acc0);
        DOMMA(acc0, 0);
        #pragma unroll 2
        for (int ntpp = 0; ntpp < 15; ntpp++) {
            const int e = 2 * ntpp;
            ZEROACC(acc1);
            DOMMA(acc1, e + 1);
            TRACK(acc0, e);
            ZEROACC(acc0);
            DOMMA(acc0, e + 2);
            TRACK(acc1, e + 1);
        }
        ZEROACC(acc1);
        DOMMA(acc1, 31);
        TRACK(acc0, 30);
        TRACK(acc1, 31);

        // ---------- issue next tile's z LDGs (overlap with epilogue) ----------
        {
            int ntile = tile + GRID;
            if (ntile >= NTILES) ntile = tile;       // dummy valid address
            const int nn = ntile * CTA_M + arow;
            const int nb = nn >> 12, nr = nn & 4095;
            const float* znp = z_e + (size_t)nb * (DIMS * HT) + nr + (size_t)(ahalf * 32) * HT;
            #pragma unroll
            for (int d = 0; d < 16; d++) {
                zraw[d]  = __ldg(znp + (size_t)(2 * d) * HT);
                zraw2[d] = __ldg(znp + (size_t)(2 * d + 1) * HT);
            }
        }

        // ---------- merge max(dot) across the 4 quad lanes ----------
        #pragma unroll
        for (int off = 1; off <= 2; off <<= 1) {
            #pragma unroll
            for (int s = 0; s < 2; s++) {
                float om = __shfl_xor_sync(0xffffffffu, m1[s], off);
                int   oi = __shfl_xor_sync(0xffffffffu, i1[s], off);
                bool take = (om > m1[s]) || (om == m1[s] && oi < i1[s]);
                if (take) { m1[s] = om; i1[s] = oi; }
            }
        }
        // shuffle-based bi for this thread's row (same warp owns it)
        int bi;
        {
            const int rr = (tid >> 1) & 15;          // row within this warp's m-tile
            const int src = 4 * (rr & 7);
            int v0 = __shfl_sync(0xffffffffu, i1[0], src);
            int v1 = __shfl_sync(0xffffffffu, i1[1], src);
            bi = (rr >> 3) ? v1 : v0;
        }

        // ---------- outputs (half-row per thread) ----------
        float* op = out + (size_t)b * (DIMS * HT) + r + (size_t)(ahalf * 32) * HT;
        float csum = 0.f;
        #pragma unroll
        for (int dg = 0; dg < 8; dg++) {
            uint32_t zo = SW(arow * 128 + ahalf * 64 + dg * 8);
            uint2 zh = *(uint2*)(smem + SM_AHI + zo);
            uint2 zl = *(uint2*)(smem + SM_ALO + zo);
            float2 z01 = u2f(zh.x), zl01 = u2f(zl.x), z23 = u2f(zh.y), zl23 = u2f(zl.y);
            float zv0 = z01.x + zl01.x, zv1 = z01.y + zl01.y;
            float zv2 = z23.x + zl23.x, zv3 = z23.y + zl23.y;
            uint32_t qo = SW(bi * 128 + ahalf * 64 + dg * 8);
            uint2 qh = *(uint2*)(smem + SM_BHI + qo);
            uint2 ql = *(uint2*)(smem + SM_BLO + qo);
            float2 e01 = u2f(qh.x), el01 = u2f(ql.x), e23 = u2f(qh.y), el23 = u2f(ql.y);
            float q0 = e01.x + el01.x, q1 = e01.y + el01.y, q2 = e23.x + el23.x, q3 = e23.y + el23.y;
            float d0 = q0 - zv0, d1v = q1 - zv1, d2v = q2 - zv2, d3 = q3 - zv3;
            op[(4 * dg + 0) * HT] = zv0 + d0;
            op[(4 * dg + 1) * HT] = zv1 + d1v;
            op[(4 * dg + 2) * HT] = zv2 + d2v;
            op[(4 * dg + 3) * HT] = zv3 + d3;
            csum += d0 * d0 + d1v * d1v + d2v * d2v + d3 * d3;
        }
        if (ahalf == 0) {
            out[ZQ_SIZE + 1 + n] = (float)bi;
            atomicAdd(&g_counts[bi], 1);
        }
        csum_total += csum;

        __syncthreads();   // protect A smem before next tile's A-fill
    }

    // ---------- per-CTA commitment partial ----------
    #pragma unroll
    for (int off = 16; off; off >>= 1)
        csum_total += __shfl_down_sync(0xffffffffu, csum_total, off);
    float* wsum = (float*)(smem + SM_WSUM);
    if (lid == 0) wsum[wid] = csum_total;
    __syncthreads();
    if (tid == 0) {
        float s = 0.f;
        #pragma unroll
        for (int w = 0; w < 8; w++) s += wsum[w];
        g_part[blockIdx.x] = s;
    }

    // ---------- last-CTA in-kernel finalize ----------
    __threadfence();
    __shared__ int s_last;
    if (tid == 0) s_last = (atomicAdd(&g_done, 1) == GRID - 1);
    __syncthreads();
    if (s_last) {
        __threadfence();
        float* red = (float*)(smem + SM_RED);

        // commitment
        red[tid] = (tid < GRID) ? g_part[tid] : 0.f;
        __syncthreads();
        #pragma unroll
        for (int off = 128; off; off >>= 1) {
            if (tid < off) red[tid] += red[tid + off];
            __syncthreads();
        }
        if (tid == 0) out[ZQ_SIZE] = 0.25f * red[0] / (float)ZQ_SIZE;
        __syncthreads();

        // entropy -> perplexity (512 codes, 2 per thread)
        const int c0 = g_counts[tid], c1 = g_counts[tid + 256];
        {
            float p0 = (float)c0 / (float)N_VEC, p1 = (float)c1 / (float)N_VEC;
            red[tid] = -p0 * logf(p0 + 1e-12f) - p1 * logf(p1 + 1e-12f);
        }
        __syncthreads();
        #pragma unroll
        for (int off = 128; off; off >>= 1) {
            if (tid < off) red[tid] += red[tid + off];
            __syncthreads();
        }
        if (tid == 0) out[ZQ_SIZE + 1 + N_VEC] = expf(red[0]);
        __syncthreads();

        // usage
        red[tid] = ((c0 > 0) ? 1.f : 0.f) + ((c1 > 0) ? 1.f : 0.f);
        __syncthreads();
        #pragma unroll
        for (int off = 128; off; off >>= 1) {
            if (tid < off) red[tid] += red[tid + off];
            __syncthreads();
        }
        if (tid == 0) out[ZQ_SIZE + 1 + N_VEC + 1] = red[0] / (float)NUM_CODES;

        // reset state for next graph replay
        g_counts[tid] = 0;
        g_counts[tid + 256] = 0;
        if (tid == 0) g_done = 0;
    }
}

extern "C" void kernel_launch(void* const* d_in, const int* in_sizes, int n_in,
                              void* d_out, int out_size) {
    const float* z_e   = (const float*)d_in[0];
    const float* embed = (const float*)d_in[1];
    float* out = (float*)d_out;

    cudaFuncSetAttribute(vq_main, cudaFuncAttributeMaxDynamicSharedMemorySize, SMEM_TOTAL);
    vq_main<<<GRID, THREADS, SMEM_TOTAL>>>(z_e, embed, out);
}